// round 12
// baseline (speedup 1.0000x reference)
#include <cuda_runtime.h>
#include <cuda_fp16.h>
#include <cstdint>

#define TOKENS 32768
#define DIN    1024
#define DOUT   1024
#define RANK   16

// ---------------- global scratch ----------------
__device__ __half g_whi[DOUT * DIN];             // 2 MB folded fp16 weight

// ---------------- fold W + LoRA, convert to fp16 ----------------
__global__ __launch_bounds__(256)
void build_w_kernel(const float* __restrict__ W,
                    const float* __restrict__ A1, const float* __restrict__ B1,
                    const float* __restrict__ A2, const float* __restrict__ B2) {
    int idx = blockIdx.x * 256 + threadIdx.x;   // 0 .. DOUT*DIN-1
    int o = idx >> 10;
    int i = idx & 1023;
    float s1 = 0.f, s2 = 0.f;
#pragma unroll
    for (int r = 0; r < RANK; ++r) {
        s1 = fmaf(B1[o * RANK + r], A1[r * DIN + i], s1);
        s2 = fmaf(B2[o * RANK + r], A2[r * DIN + i], s2);
    }
    float w = W[idx] + 0.5f * s1 + s2;          // SCALE1=8/16, SCALE2=16/16
    g_whi[idx] = __float2half_rn(w);
}

// ---------------- fused GEMM: out = fp16(x) @ whi^T + b ----------------
// CTA tile 128m x 256n, 8 warps of 64x64, 4-stage cp.async for W,
// x converted fp32->fp16 in-register inside the mainloop (no split_x pass).
#define BK      32
#define STAGES  4
#define XO      0                  // x tile: 128 x 32 fp16 = 8 KB
#define WO      8192               // w tile: 256 x 32 fp16 = 16 KB
#define STG     24576
#define NKT     (DIN / BK)         // 32

__device__ __forceinline__ uint32_t smem_u32(const void* p) {
    uint32_t a;
    asm("{ .reg .u64 t; cvta.to.shared.u64 t, %1; cvt.u32.u64 %0, t; }" : "=r"(a) : "l"(p));
    return a;
}
__device__ __forceinline__ uint32_t swz64(uint32_t o) { return o ^ ((o >> 3) & 0x30); }

__device__ __forceinline__ void ldsm4(uint32_t* r, uint32_t addr) {
    asm volatile("ldmatrix.sync.aligned.m8n8.x4.shared.b16 {%0,%1,%2,%3}, [%4];"
        : "=r"(r[0]), "=r"(r[1]), "=r"(r[2]), "=r"(r[3]) : "r"(addr));
}
__device__ __forceinline__ void mma16816(float* c, const uint32_t* a, const uint32_t* b) {
    asm volatile("mma.sync.aligned.m16n8k16.row.col.f32.f16.f16.f32 "
        "{%0,%1,%2,%3}, {%4,%5,%6,%7}, {%8,%9}, {%0,%1,%2,%3};"
        : "+f"(c[0]), "+f"(c[1]), "+f"(c[2]), "+f"(c[3])
        : "r"(a[0]), "r"(a[1]), "r"(a[2]), "r"(a[3]), "r"(b[0]), "r"(b[1]));
}

#define CP16(dst, src) \
    asm volatile("cp.async.cg.shared.global [%0], [%1], 16;" :: "r"(dst), "l"(src))
#define CP_COMMIT() asm volatile("cp.async.commit_group;")
#define CP_WAIT2()  asm volatile("cp.async.wait_group 2;")

__global__ void __launch_bounds__(256, 1)
gemm_fused(const float* __restrict__ X, const float* __restrict__ bias,
           float* __restrict__ out) {
    extern __shared__ char sm[];
    const uint32_t sb = smem_u32(sm);
    const int tid  = threadIdx.x;
    const int lane = tid & 31;
    const int wid  = tid >> 5;
    const int wm   = wid & 1;        // 2 m-groups of 64
    const int wn   = wid >> 1;       // 4 n-groups of 64
    const int m0   = blockIdx.y * 128;
    const int n0   = blockIdx.x * 256;

    // W cp.async mapping: rows tid/4 (+64,+128,+192), 16B chunk col tid%4
    const int crow = tid >> 2;
    const int ccol = tid & 3;
    const __half* gwh = g_whi + (size_t)(n0 + crow) * DIN + ccol * 8;
    const uint32_t wsts = swz64((uint32_t)crow * 64 + (uint32_t)ccol * 16);

    // x fp32 LDG mapping: row tid/2, k-half tid%2 (16 fp32 each)
    const int xrow = tid >> 1;
    const int xkh  = tid & 1;
    const float* xg = X + (size_t)(m0 + xrow) * DIN + xkh * 16;
    const uint32_t xsts0 = swz64((uint32_t)xrow * 64 + (uint32_t)xkh * 32);
    const uint32_t xsts1 = swz64((uint32_t)xrow * 64 + (uint32_t)xkh * 32 + 16);

    // ldmatrix lane offsets (unswizzled; ks added pre-swizzle)
    const uint32_t a_off = (uint32_t)(wm * 64 + (lane & 15)) * 64 + (uint32_t)(lane >> 4) * 16;
    const uint32_t b_off = (uint32_t)(wn * 64 + (lane >> 4) * 8 + (lane & 7)) * 64 +
                           (uint32_t)((lane >> 3) & 1) * 16;

    float acc[4][8][4];
#pragma unroll
    for (int mt = 0; mt < 4; ++mt)
#pragma unroll
        for (int nt = 0; nt < 8; ++nt)
#pragma unroll
            for (int c = 0; c < 4; ++c) acc[mt][nt][c] = 0.f;

#define ISSUE_W(kt) do {                                                           \
        const uint32_t st_ = sb + WO + ((kt) % STAGES) * STG;                      \
        const size_t go_ = (size_t)(kt) * BK;                                      \
        CP16(st_ + wsts,         gwh + go_);                                       \
        CP16(st_ + wsts + 4096,  gwh + go_ + (size_t)64  * DIN);                   \
        CP16(st_ + wsts + 8192,  gwh + go_ + (size_t)128 * DIN);                   \
        CP16(st_ + wsts + 12288, gwh + go_ + (size_t)192 * DIN);                   \
    } while (0)

    // cvt 16 fp32 -> 16 fp16, STS into stage slot
#define XCVT_STS(kt, f) do {                                                       \
        const uint32_t st_ = sb + XO + ((kt) % STAGES) * STG;                      \
        union { __half2 h2[8]; uint4 q[2]; } U;                                    \
        U.h2[0] = __floats2half2_rn((f)[0].x, (f)[0].y);                           \
        U.h2[1] = __floats2half2_rn((f)[0].z, (f)[0].w);                           \
        U.h2[2] = __floats2half2_rn((f)[1].x, (f)[1].y);                           \
        U.h2[3] = __floats2half2_rn((f)[1].z, (f)[1].w);                           \
        U.h2[4] = __floats2half2_rn((f)[2].x, (f)[2].y);                           \
        U.h2[5] = __floats2half2_rn((f)[2].z, (f)[2].w);                           \
        U.h2[6] = __floats2half2_rn((f)[3].x, (f)[3].y);                           \
        U.h2[7] = __floats2half2_rn((f)[3].z, (f)[3].w);                           \
        asm volatile("st.shared.v4.b32 [%0], {%1,%2,%3,%4};" :: "r"(st_ + xsts0), \
            "r"(U.q[0].x), "r"(U.q[0].y), "r"(U.q[0].z), "r"(U.q[0].w));           \
        asm volatile("st.shared.v4.b32 [%0], {%1,%2,%3,%4};" :: "r"(st_ + xsts1), \
            "r"(U.q[1].x), "r"(U.q[1].y), "r"(U.q[1].z), "r"(U.q[1].w));           \
    } while (0)

    // prologue: W stages 0-2 async, x stages 0-2 sync (LDG+cvt+STS)
#pragma unroll
    for (int p = 0; p < 3; ++p) {
        ISSUE_W(p); CP_COMMIT();
        float4 f[4];
        const float4* xp = reinterpret_cast<const float4*>(xg + p * BK);
#pragma unroll
        for (int i = 0; i < 4; ++i) f[i] = xp[i];
        XCVT_STS(p, f);
    }

#pragma unroll 1
    for (int kt = 0; kt < NKT; ++kt) {
        CP_WAIT2();
        __syncthreads();

        const bool pf = (kt + 3 < NKT);
        float4 xf[4];
        if (pf) {
            const float4* xp = reinterpret_cast<const float4*>(xg + (kt + 3) * BK);
#pragma unroll
            for (int i = 0; i < 4; ++i) xf[i] = xp[i];   // LDG hidden under compute
            ISSUE_W(kt + 3);
        }
        CP_COMMIT();

        const uint32_t stx = sb + XO + (kt % STAGES) * STG;
        const uint32_t stw = sb + WO + (kt % STAGES) * STG;
#pragma unroll
        for (int s = 0; s < 2; ++s) {
            const uint32_t ks = s * 32;
            const uint32_t a_sw = swz64(a_off + ks);
            const uint32_t b_sw = swz64(b_off + ks);

            uint32_t bh[4][4];
#pragma unroll
            for (int j = 0; j < 4; ++j)
                ldsm4(bh[j], stw + b_sw + j * 1024);

            uint32_t ah[4][4];
#pragma unroll
            for (int mt = 0; mt < 4; ++mt)
                ldsm4(ah[mt], stx + a_sw + mt * 1024);

#pragma unroll
            for (int mt = 0; mt < 4; ++mt)
#pragma unroll
                for (int nt = 0; nt < 8; ++nt)
                    mma16816(acc[mt][nt], ah[mt], &bh[nt >> 1][(nt & 1) * 2]);
        }

        if (pf) XCVT_STS(kt + 3, xf);   // slot (kt-1)%4 freed by this iter's barrier
    }

    // ---- epilogue: add bias, store fp32 (float2) ----
    const int erow = m0 + wm * 64 + (lane >> 2);
    const int ecol = n0 + wn * 64 + (lane & 3) * 2;
#pragma unroll
    for (int nt = 0; nt < 8; ++nt) {
        const int c = ecol + nt * 8;
        const float b0 = bias[c], b1 = bias[c + 1];
#pragma unroll
        for (int mt = 0; mt < 4; ++mt) {
            const int r = erow + mt * 16;
            float2 o0 = make_float2(acc[mt][nt][0] + b0, acc[mt][nt][1] + b1);
            float2 o1 = make_float2(acc[mt][nt][2] + b0, acc[mt][nt][3] + b1);
            *reinterpret_cast<float2*>(out + (size_t)r * DOUT + c)       = o0;
            *reinterpret_cast<float2*>(out + (size_t)(r + 8) * DOUT + c) = o1;
        }
    }
}

// ---------------- launch ----------------
extern "C" void kernel_launch(void* const* d_in, const int* in_sizes, int n_in,
                              void* d_out, int out_size) {
    const float* x  = (const float*)d_in[0];
    const float* W  = (const float*)d_in[1];
    const float* b  = (const float*)d_in[2];
    const float* A1 = (const float*)d_in[3];
    const float* B1 = (const float*)d_in[4];
    const float* A2 = (const float*)d_in[5];
    const float* B2 = (const float*)d_in[6];
    float* out = (float*)d_out;

    cudaFuncSetAttribute(gemm_fused, cudaFuncAttributeMaxDynamicSharedMemorySize,
                         STAGES * STG);

    build_w_kernel<<<(DOUT * DIN) / 256, 256>>>(W, A1, B1, A2, B2);

    dim3 grid(DOUT / 256, TOKENS / 128);   // (n-tiles=4, m-tiles=256)
    gemm_fused<<<grid, 256, STAGES * STG>>>(x, b, out);
}